// round 5
// baseline (speedup 1.0000x reference)
#include <cuda_runtime.h>
#include <cuda_bf16.h>
#include <cstdint>

// ---------------- problem dims ----------------
#define TOKENS 8192
#define OUTF   4096
#define INF    4096
#define GROUPS 512
#define LUTK   16
#define VEC    8

// ---------------- GEMM tiling ----------------
#define MTILE  128
#define NTILE  128
#define BK     32                   // bf16 K elements per chunk (64B per row)
#define NCHUNKS (INF / BK)          // 128
#define ROWB   80                   // padded smem row bytes (64 data + 16 pad)
#define TILEB  (128 * ROWB)         // 10240 bytes per 128x32 bf16 tile
#define OFF_AH 0
#define OFF_AL (1 * TILEB)
#define OFF_BH (2 * TILEB)
#define OFF_BL (3 * TILEB)
#define STAGEB (4 * TILEB)          // 40960
#define SMEM_BYTES (2 * STAGEB)     // 81920 (2 stages)

// ---------------- device scratch (allocation-free rule: __device__ globals) ----------------
__device__ __nv_bfloat16 g_xhi[TOKENS * INF];
__device__ __nv_bfloat16 g_xlo[TOKENS * INF];
__device__ __nv_bfloat16 g_whi[OUTF * INF];
__device__ __nv_bfloat16 g_wlo[OUTF * INF];

// ---------------- PTX helpers (base compute_103 target only: NO tcgen05) ----------------
static __device__ __forceinline__ uint32_t smem_u32(const void* p) {
    uint32_t a;
    asm("{ .reg .u64 t; cvta.to.shared.u64 t, %1; cvt.u32.u64 %0, t; }" : "=r"(a) : "l"(p));
    return a;
}

#define CP16(smem_addr, gptr) \
    asm volatile("cp.async.cg.shared.global [%0], [%1], 16;" \
                 :: "r"(smem_addr), "l"(gptr) : "memory")
#define CP_COMMIT() asm volatile("cp.async.commit_group;" ::: "memory")
#define CP_WAIT1()  asm volatile("cp.async.wait_group 1;" ::: "memory")
#define CP_WAIT0()  asm volatile("cp.async.wait_group 0;" ::: "memory")

#define LDSM_X4(r0, r1, r2, r3, addr) \
    asm volatile("ldmatrix.sync.aligned.m8n8.x4.shared.b16 {%0,%1,%2,%3}, [%4];" \
                 : "=r"(r0), "=r"(r1), "=r"(r2), "=r"(r3) : "r"(addr))

#define MMA_BF16(d, a, b) \
    asm volatile("mma.sync.aligned.m16n8k16.row.col.f32.bf16.bf16.f32 " \
                 "{%0,%1,%2,%3}, {%4,%5,%6,%7}, {%8,%9}, {%0,%1,%2,%3};" \
                 : "+f"((d)[0]), "+f"((d)[1]), "+f"((d)[2]), "+f"((d)[3]) \
                 : "r"((a)[0]), "r"((a)[1]), "r"((a)[2]), "r"((a)[3]), \
                   "r"((b)[0]), "r"((b)[1]))

// ---------------- Kernel 1: split x (fp32 -> bf16 hi/lo) ----------------
__global__ void __launch_bounds__(256) split_x_kernel(const float* __restrict__ x) {
    int gid = blockIdx.x * blockDim.x + threadIdx.x;   // float4 index
    float4 v = ((const float4*)x)[gid];
    __nv_bfloat162 h01 = __floats2bfloat162_rn(v.x, v.y);
    __nv_bfloat162 h23 = __floats2bfloat162_rn(v.z, v.w);
    __nv_bfloat162 l01 = __floats2bfloat162_rn(v.x - __low2float(h01), v.y - __high2float(h01));
    __nv_bfloat162 l23 = __floats2bfloat162_rn(v.z - __low2float(h23), v.w - __high2float(h23));
    uint2 uh, ul;
    uh.x = *reinterpret_cast<unsigned int*>(&h01);
    uh.y = *reinterpret_cast<unsigned int*>(&h23);
    ul.x = *reinterpret_cast<unsigned int*>(&l01);
    ul.y = *reinterpret_cast<unsigned int*>(&l23);
    ((uint2*)g_xhi)[gid] = uh;
    ((uint2*)g_xlo)[gid] = ul;
}

// ---------------- Kernel 2: build weight (softmax-LUT mix -> bf16 hi/lo) ----------------
__global__ void __launch_bounds__(256) build_w_kernel(const float* __restrict__ logits,
                                                      const float* __restrict__ luts) {
    int idx = blockIdx.x * blockDim.x + threadIdx.x;   // o fastest: warp shares g's LUT
    int o = idx & (OUTF - 1);
    int g = idx >> 12;

    float acc[VEC];
#pragma unroll
    for (int v = 0; v < VEC; ++v) acc[v] = 0.f;

#pragma unroll
    for (int n = 0; n < 2; ++n) {
        const float4* lg = (const float4*)(logits + (((size_t)n * OUTF + o) * GROUPS + g) * LUTK);
        float4 t0 = lg[0], t1 = lg[1], t2 = lg[2], t3 = lg[3];
        float l[LUTK] = {t0.x, t0.y, t0.z, t0.w, t1.x, t1.y, t1.z, t1.w,
                         t2.x, t2.y, t2.z, t2.w, t3.x, t3.y, t3.z, t3.w};
        float m = l[0];
#pragma unroll
        for (int k = 1; k < LUTK; ++k) m = fmaxf(m, l[k]);
        float s = 0.f;
#pragma unroll
        for (int k = 0; k < LUTK; ++k) { l[k] = __expf(l[k] - m); s += l[k]; }
        float inv = __frcp_rn(s);
        const float4* lut4 = (const float4*)(luts + ((size_t)n * GROUPS + g) * LUTK * VEC);
#pragma unroll
        for (int k = 0; k < LUTK; ++k) {
            float wgt = l[k] * inv;
            float4 a = lut4[k * 2 + 0];
            float4 b = lut4[k * 2 + 1];
            acc[0] += wgt * a.x; acc[1] += wgt * a.y; acc[2] += wgt * a.z; acc[3] += wgt * a.w;
            acc[4] += wgt * b.x; acc[5] += wgt * b.y; acc[6] += wgt * b.z; acc[7] += wgt * b.w;
        }
    }

    union { uint4 u; __nv_bfloat16 h[8]; } ph, pl;
#pragma unroll
    for (int v = 0; v < VEC; ++v) {
        __nv_bfloat16 h = __float2bfloat16_rn(acc[v]);
        ph.h[v] = h;
        pl.h[v] = __float2bfloat16_rn(acc[v] - __bfloat162float(h));
    }
    ((uint4*)g_whi)[(size_t)o * (INF / 8) + g] = ph.u;
    ((uint4*)g_wlo)[(size_t)o * (INF / 8) + g] = pl.u;
}

// ---------------- Kernel 3: split-bf16 HMMA GEMM ----------------
// C[8192,4096] = X @ W^T + bias via (xh+xl)(wh+wl)^T, dropping lo*lo (~1.5e-5 rel).
// 128x128 CTA tile, BK=32, 4 warps (2x2 grid, warp tile 64x64), 2-stage cp.async pipe.
__global__ void __launch_bounds__(128, 2)
gemm_split_kernel(const float* __restrict__ bias, float* __restrict__ out) {
    extern __shared__ char smem[];
    uint32_t sbase = smem_u32(smem);

    const int tid  = threadIdx.x;
    const int wid  = tid >> 5;
    const int lane = tid & 31;
    const int wm   = wid >> 1;       // 0..1  (M warp row)
    const int wn   = wid & 1;        // 0..1  (N warp col)

    const int m0 = blockIdx.y * MTILE;
    const int n0 = blockIdx.x * NTILE;

    // ---- per-lane ldmatrix address offsets (within a 16x16 frag at 80B rows) ----
    const int g8 = lane >> 3, r8 = lane & 7;
    // A frags: matrices (m0-7,k0-7),(m8-15,k0-7),(m0-7,k8-15),(m8-15,k8-15)
    const uint32_t aOff = (uint32_t)(((g8 & 1) * 8 + r8) * ROWB + (g8 >> 1) * 16);
    // B frags: matrices (n0-7,k0-7),(n0-7,k8-15),(n8-15,k0-7),(n8-15,k8-15)
    const uint32_t bOff = (uint32_t)(((g8 >> 1) * 8 + r8) * ROWB + (g8 & 1) * 16);
    const uint32_t wmRow = (uint32_t)(wm * 64 * ROWB);
    const uint32_t wnRow = (uint32_t)(wn * 64 * ROWB);

    // ---- gmem source rows for this thread's cp.async (row = tid, 0..127) ----
    const char* pxh = (const char*)(g_xhi + (size_t)(m0 + tid) * INF);
    const char* pxl = (const char*)(g_xlo + (size_t)(m0 + tid) * INF);
    const char* pwh = (const char*)(g_whi + (size_t)(n0 + tid) * INF);
    const char* pwl = (const char*)(g_wlo + (size_t)(n0 + tid) * INF);
    const uint32_t dstRow = sbase + (uint32_t)tid * ROWB;

    float acc[4][8][4];
#pragma unroll
    for (int mt = 0; mt < 4; ++mt)
#pragma unroll
        for (int nt = 0; nt < 8; ++nt)
#pragma unroll
            for (int e = 0; e < 4; ++e) acc[mt][nt][e] = 0.f;

    // ---- load chunk c into stage s ----
    auto load_chunk = [&](int c, int s) {
        uint32_t d = dstRow + (uint32_t)s * STAGEB;
        size_t go = (size_t)c * (BK * 2);   // byte offset within row
#pragma unroll
        for (int q = 0; q < 4; ++q) {
            CP16(d + OFF_AH + q * 16, pxh + go + q * 16);
            CP16(d + OFF_AL + q * 16, pxl + go + q * 16);
            CP16(d + OFF_BH + q * 16, pwh + go + q * 16);
            CP16(d + OFF_BL + q * 16, pwl + go + q * 16);
        }
        CP_COMMIT();
    };

    load_chunk(0, 0);

    int s = 0;
    for (int c = 0; c < NCHUNKS; ++c) {
        if (c + 1 < NCHUNKS) {
            load_chunk(c + 1, s ^ 1);
            CP_WAIT1();
        } else {
            CP_WAIT0();
        }
        __syncthreads();

        const uint32_t st = sbase + (uint32_t)s * STAGEB;
#pragma unroll
        for (int ks = 0; ks < 2; ++ks) {
            const uint32_t kofs = (uint32_t)ks * 32;
            uint32_t Ah[4][4], Al[4][4], Bh[8][2], Bl[8][2];
#pragma unroll
            for (int mt = 0; mt < 4; ++mt) {
                uint32_t a = st + wmRow + (uint32_t)(mt * 16 * ROWB) + aOff + kofs;
                LDSM_X4(Ah[mt][0], Ah[mt][1], Ah[mt][2], Ah[mt][3], a + OFF_AH);
                LDSM_X4(Al[mt][0], Al[mt][1], Al[mt][2], Al[mt][3], a + OFF_AL);
            }
#pragma unroll
            for (int nt2 = 0; nt2 < 4; ++nt2) {
                uint32_t b = st + wnRow + (uint32_t)(nt2 * 16 * ROWB) + bOff + kofs;
                uint32_t r0, r1, r2, r3;
                LDSM_X4(r0, r1, r2, r3, b + OFF_BH);
                Bh[nt2 * 2][0] = r0; Bh[nt2 * 2][1] = r1;
                Bh[nt2 * 2 + 1][0] = r2; Bh[nt2 * 2 + 1][1] = r3;
                LDSM_X4(r0, r1, r2, r3, b + OFF_BL);
                Bl[nt2 * 2][0] = r0; Bl[nt2 * 2][1] = r1;
                Bl[nt2 * 2 + 1][0] = r2; Bl[nt2 * 2 + 1][1] = r3;
            }
            // pass-major order: consecutive MMAs never share an accumulator
#pragma unroll
            for (int mt = 0; mt < 4; ++mt)
#pragma unroll
                for (int nt = 0; nt < 8; ++nt)
                    MMA_BF16(acc[mt][nt], Ah[mt], Bh[nt]);
#pragma unroll
            for (int mt = 0; mt < 4; ++mt)
#pragma unroll
                for (int nt = 0; nt < 8; ++nt)
                    MMA_BF16(acc[mt][nt], Ah[mt], Bl[nt]);
#pragma unroll
            for (int mt = 0; mt < 4; ++mt)
#pragma unroll
                for (int nt = 0; nt < 8; ++nt)
                    MMA_BF16(acc[mt][nt], Al[mt], Bh[nt]);
        }
        __syncthreads();
        s ^= 1;
    }

    // ---- epilogue: acc + bias -> out ----
    const int cgl = (lane & 3) * 2;
    const int r0l = lane >> 2;
    const float* bp = bias + n0 + wn * 64 + cgl;
    float2 bv[8];
#pragma unroll
    for (int nt = 0; nt < 8; ++nt) bv[nt] = *(const float2*)(bp + nt * 8);

#pragma unroll
    for (int mt = 0; mt < 4; ++mt) {
        size_t row = (size_t)(m0 + wm * 64 + mt * 16 + r0l);
        float* p0 = out + row * OUTF + n0 + wn * 64 + cgl;
        float* p1 = p0 + (size_t)8 * OUTF;
#pragma unroll
        for (int nt = 0; nt < 8; ++nt) {
            float2 v0 = {acc[mt][nt][0] + bv[nt].x, acc[mt][nt][1] + bv[nt].y};
            float2 v1 = {acc[mt][nt][2] + bv[nt].x, acc[mt][nt][3] + bv[nt].y};
            *(float2*)(p0 + nt * 8) = v0;
            *(float2*)(p1 + nt * 8) = v1;
        }
    }
}

// ---------------- launcher ----------------
extern "C" void kernel_launch(void* const* d_in, const int* in_sizes, int n_in,
                              void* d_out, int out_size) {
    const float* x      = (const float*)d_in[0];
    const float* logits = (const float*)d_in[1];
    const float* luts   = (const float*)d_in[2];
    const float* bias   = (const float*)d_in[3];
    float* out          = (float*)d_out;
    (void)in_sizes; (void)n_in; (void)out_size;

    split_x_kernel<<<(TOKENS * INF / 4) / 256, 256>>>(x);
    build_w_kernel<<<(OUTF * GROUPS) / 256, 256>>>(logits, luts);

    cudaFuncSetAttribute(gemm_split_kernel, cudaFuncAttributeMaxDynamicSharedMemorySize, SMEM_BYTES);
    dim3 grid(OUTF / NTILE, TOKENS / MTILE);   // (32, 64): n fast -> W stays L2-resident
    gemm_split_kernel<<<grid, 128, SMEM_BYTES>>>(bias, out);
}

// round 8
// speedup vs baseline: 1.1018x; 1.1018x over previous
#include <cuda_runtime.h>
#include <cuda_bf16.h>
#include <cstdint>

// ---------------- problem dims ----------------
#define TOKENS 8192
#define OUTF   4096
#define INF    4096
#define GROUPS 512
#define LUTK   16
#define VEC    8

// ---------------- GEMM tiling ----------------
#define MTILE  256
#define NTILE  128
#define BK     32                   // bf16 K elements per chunk (64B data per row)
#define NCHUNKS (INF / BK)          // 128
#define ROWB   80                   // padded smem row bytes (64 data + 16 pad) -> conflict-free ldsm
#define ATILEB (256 * ROWB)         // 20480 B  (256 rows)
#define BTILEB (128 * ROWB)         // 10240 B  (128 rows)
#define OFF_AH 0
#define OFF_AL (ATILEB)
#define OFF_BH (2 * ATILEB)
#define OFF_BL (2 * ATILEB + BTILEB)
#define STAGEB (2 * ATILEB + 2 * BTILEB)   // 61440
#define NSTAGE 3
#define SMEM_BYTES (NSTAGE * STAGEB)       // 184320

// ---------------- device scratch (allocation-free rule: __device__ globals) ----------------
__device__ __nv_bfloat16 g_xhi[TOKENS * INF];
__device__ __nv_bfloat16 g_xlo[TOKENS * INF];
__device__ __nv_bfloat16 g_whi[OUTF * INF];
__device__ __nv_bfloat16 g_wlo[OUTF * INF];

// ---------------- PTX helpers (base compute_103 target: NO tcgen05/TMEM) ----------------
static __device__ __forceinline__ uint32_t smem_u32(const void* p) {
    uint32_t a;
    asm("{ .reg .u64 t; cvta.to.shared.u64 t, %1; cvt.u32.u64 %0, t; }" : "=r"(a) : "l"(p));
    return a;
}

#define CP16(smem_addr, gptr) \
    asm volatile("cp.async.cg.shared.global [%0], [%1], 16;" \
                 :: "r"(smem_addr), "l"(gptr) : "memory")
#define CP_COMMIT() asm volatile("cp.async.commit_group;" ::: "memory")
#define CP_WAIT1()  asm volatile("cp.async.wait_group 1;" ::: "memory")
#define CP_WAIT0()  asm volatile("cp.async.wait_group 0;" ::: "memory")

#define LDSM_X4(r0, r1, r2, r3, addr) \
    asm volatile("ldmatrix.sync.aligned.m8n8.x4.shared.b16 {%0,%1,%2,%3}, [%4];" \
                 : "=r"(r0), "=r"(r1), "=r"(r2), "=r"(r3) : "r"(addr))

#define MMA_BF16(d, a, b) \
    asm volatile("mma.sync.aligned.m16n8k16.row.col.f32.bf16.bf16.f32 " \
                 "{%0,%1,%2,%3}, {%4,%5,%6,%7}, {%8,%9}, {%0,%1,%2,%3};" \
                 : "+f"((d)[0]), "+f"((d)[1]), "+f"((d)[2]), "+f"((d)[3]) \
                 : "r"((a)[0]), "r"((a)[1]), "r"((a)[2]), "r"((a)[3]), \
                   "r"((b)[0]), "r"((b)[1]))

// ---------------- Kernel 1: split x (fp32 -> bf16 hi/lo) ----------------
__global__ void __launch_bounds__(256) split_x_kernel(const float* __restrict__ x) {
    int gid = blockIdx.x * blockDim.x + threadIdx.x;   // float4 index
    float4 v = ((const float4*)x)[gid];
    __nv_bfloat162 h01 = __floats2bfloat162_rn(v.x, v.y);
    __nv_bfloat162 h23 = __floats2bfloat162_rn(v.z, v.w);
    __nv_bfloat162 l01 = __floats2bfloat162_rn(v.x - __low2float(h01), v.y - __high2float(h01));
    __nv_bfloat162 l23 = __floats2bfloat162_rn(v.z - __low2float(h23), v.w - __high2float(h23));
    uint2 uh, ul;
    uh.x = *reinterpret_cast<unsigned int*>(&h01);
    uh.y = *reinterpret_cast<unsigned int*>(&h23);
    ul.x = *reinterpret_cast<unsigned int*>(&l01);
    ul.y = *reinterpret_cast<unsigned int*>(&l23);
    ((uint2*)g_xhi)[gid] = uh;
    ((uint2*)g_xlo)[gid] = ul;
}

// ---------------- Kernel 2: build weight (softmax-LUT mix -> bf16 hi/lo) ----------------
__global__ void __launch_bounds__(256) build_w_kernel(const float* __restrict__ logits,
                                                      const float* __restrict__ luts) {
    int idx = blockIdx.x * blockDim.x + threadIdx.x;   // o fastest: warp shares g's LUT
    int o = idx & (OUTF - 1);
    int g = idx >> 12;

    float acc[VEC];
#pragma unroll
    for (int v = 0; v < VEC; ++v) acc[v] = 0.f;

#pragma unroll
    for (int n = 0; n < 2; ++n) {
        const float4* lg = (const float4*)(logits + (((size_t)n * OUTF + o) * GROUPS + g) * LUTK);
        float4 t0 = lg[0], t1 = lg[1], t2 = lg[2], t3 = lg[3];
        float l[LUTK] = {t0.x, t0.y, t0.z, t0.w, t1.x, t1.y, t1.z, t1.w,
                         t2.x, t2.y, t2.z, t2.w, t3.x, t3.y, t3.z, t3.w};
        float m = l[0];
#pragma unroll
        for (int k = 1; k < LUTK; ++k) m = fmaxf(m, l[k]);
        float s = 0.f;
#pragma unroll
        for (int k = 0; k < LUTK; ++k) { l[k] = __expf(l[k] - m); s += l[k]; }
        float inv = __frcp_rn(s);
        const float4* lut4 = (const float4*)(luts + ((size_t)n * GROUPS + g) * LUTK * VEC);
#pragma unroll
        for (int k = 0; k < LUTK; ++k) {
            float wgt = l[k] * inv;
            float4 a = lut4[k * 2 + 0];
            float4 b = lut4[k * 2 + 1];
            acc[0] += wgt * a.x; acc[1] += wgt * a.y; acc[2] += wgt * a.z; acc[3] += wgt * a.w;
            acc[4] += wgt * b.x; acc[5] += wgt * b.y; acc[6] += wgt * b.z; acc[7] += wgt * b.w;
        }
    }

    union { uint4 u; __nv_bfloat16 h[8]; } ph, pl;
#pragma unroll
    for (int v = 0; v < VEC; ++v) {
        __nv_bfloat16 h = __float2bfloat16_rn(acc[v]);
        ph.h[v] = h;
        pl.h[v] = __float2bfloat16_rn(acc[v] - __bfloat162float(h));
    }
    ((uint4*)g_whi)[(size_t)o * (INF / 8) + g] = ph.u;
    ((uint4*)g_wlo)[(size_t)o * (INF / 8) + g] = pl.u;
}

// ---------------- Kernel 3: split-bf16 HMMA GEMM ----------------
// C[8192,4096] = X @ W^T + bias via (xh+xl)(wh+wl)^T, dropping lo*lo (~1.5e-5 rel).
// 256x128 CTA tile, BK=32, 8 warps (4x2 grid, warp tile 64x64), 3-stage cp.async ring,
// ONE __syncthreads per chunk.
__global__ void __launch_bounds__(256, 1)
gemm_split_kernel(const float* __restrict__ bias, float* __restrict__ out) {
    extern __shared__ char smem[];
    uint32_t sbase = smem_u32(smem);

    const int tid  = threadIdx.x;
    const int wid  = tid >> 5;
    const int lane = tid & 31;
    const int wm   = wid >> 1;       // 0..3  (M warp row, 64 rows each)
    const int wn   = wid & 1;        // 0..1  (N warp col, 64 cols each)

    const int m0 = blockIdx.y * MTILE;
    const int n0 = blockIdx.x * NTILE;

    // ---- per-lane ldmatrix address offsets (within a 16x16 frag at 80B rows) ----
    const int g8 = lane >> 3, r8 = lane & 7;
    // A frags: matrices (m0-7,k0-7),(m8-15,k0-7),(m0-7,k8-15),(m8-15,k8-15)
    const uint32_t aOff = (uint32_t)(((g8 & 1) * 8 + r8) * ROWB + (g8 >> 1) * 16);
    // B frags: matrices (n0-7,k0-7),(n0-7,k8-15),(n8-15,k0-7),(n8-15,k8-15)
    const uint32_t bOff = (uint32_t)(((g8 >> 1) * 8 + r8) * ROWB + (g8 & 1) * 16);
    const uint32_t wmRow = (uint32_t)(wm * 64 * ROWB);
    const uint32_t wnRow = (uint32_t)(wn * 64 * ROWB);

    // ---- gmem source rows for cp.async ----
    // A: thread -> row tid (0..255), 4x16B per tile.  B: row tid>>1, half (tid&1)*32B, 2x16B.
    const char* pxh = (const char*)(g_xhi + (size_t)(m0 + tid) * INF);
    const char* pxl = (const char*)(g_xlo + (size_t)(m0 + tid) * INF);
    const char* pwh = (const char*)(g_whi + (size_t)(n0 + (tid >> 1)) * INF);
    const char* pwl = (const char*)(g_wlo + (size_t)(n0 + (tid >> 1)) * INF);
    const uint32_t aDst = sbase + (uint32_t)tid * ROWB;
    const uint32_t bDst = sbase + (uint32_t)(tid >> 1) * ROWB + (uint32_t)(tid & 1) * 32u;
    const uint32_t bSrcOff = (uint32_t)(tid & 1) * 32u;

    float acc[4][8][4];
#pragma unroll
    for (int mt = 0; mt < 4; ++mt)
#pragma unroll
        for (int nt = 0; nt < 8; ++nt)
#pragma unroll
            for (int e = 0; e < 4; ++e) acc[mt][nt][e] = 0.f;

    // ---- load chunk c into ring stage s ----
    auto load_chunk = [&](int c, int s) {
        uint32_t sb = (uint32_t)s * STAGEB;
        size_t go = (size_t)c * (BK * 2);   // byte offset within a K row
#pragma unroll
        for (int q = 0; q < 4; ++q) {
            CP16(aDst + sb + OFF_AH + q * 16, pxh + go + q * 16);
            CP16(aDst + sb + OFF_AL + q * 16, pxl + go + q * 16);
        }
#pragma unroll
        for (int q = 0; q < 2; ++q) {
            CP16(bDst + sb + OFF_BH + q * 16, pwh + go + bSrcOff + q * 16);
            CP16(bDst + sb + OFF_BL + q * 16, pwl + go + bSrcOff + q * 16);
        }
        CP_COMMIT();
    };

    load_chunk(0, 0);
    load_chunk(1, 1);

    for (int c = 0; c < NCHUNKS; ++c) {
        // ensure chunk c landed (<=1 younger group may stay in flight)
        if (c + 2 < NCHUNKS) CP_WAIT1(); else CP_WAIT0();
        __syncthreads();   // also: all warps finished reading the stage we refill below

        if (c + 2 < NCHUNKS) load_chunk(c + 2, (c + 2) % NSTAGE);

        const uint32_t st = sbase + (uint32_t)(c % NSTAGE) * STAGEB;
#pragma unroll
        for (int ks = 0; ks < 2; ++ks) {
            const uint32_t kofs = (uint32_t)ks * 32;
            uint32_t Ah[4][4], Al[4][4], Bh[8][2], Bl[8][2];
#pragma unroll
            for (int mt = 0; mt < 4; ++mt) {
                uint32_t a = st + wmRow + (uint32_t)(mt * 16 * ROWB) + aOff + kofs;
                LDSM_X4(Ah[mt][0], Ah[mt][1], Ah[mt][2], Ah[mt][3], a + OFF_AH);
                LDSM_X4(Al[mt][0], Al[mt][1], Al[mt][2], Al[mt][3], a + OFF_AL);
            }
#pragma unroll
            for (int nt2 = 0; nt2 < 4; ++nt2) {
                uint32_t b = st + wnRow + (uint32_t)(nt2 * 16 * ROWB) + bOff + kofs;
                uint32_t r0, r1, r2, r3;
                LDSM_X4(r0, r1, r2, r3, b + OFF_BH);
                Bh[nt2 * 2][0] = r0; Bh[nt2 * 2][1] = r1;
                Bh[nt2 * 2 + 1][0] = r2; Bh[nt2 * 2 + 1][1] = r3;
                LDSM_X4(r0, r1, r2, r3, b + OFF_BL);
                Bl[nt2 * 2][0] = r0; Bl[nt2 * 2][1] = r1;
                Bl[nt2 * 2 + 1][0] = r2; Bl[nt2 * 2 + 1][1] = r3;
            }
            // pass-major order: consecutive MMAs never share an accumulator
#pragma unroll
            for (int mt = 0; mt < 4; ++mt)
#pragma unroll
                for (int nt = 0; nt < 8; ++nt)
                    MMA_BF16(acc[mt][nt], Ah[mt], Bh[nt]);
#pragma unroll
            for (int mt = 0; mt < 4; ++mt)
#pragma unroll
                for (int nt = 0; nt < 8; ++nt)
                    MMA_BF16(acc[mt][nt], Ah[mt], Bl[nt]);
#pragma unroll
            for (int mt = 0; mt < 4; ++mt)
#pragma unroll
                for (int nt = 0; nt < 8; ++nt)
                    MMA_BF16(acc[mt][nt], Al[mt], Bh[nt]);
        }
    }

    // ---- epilogue: acc + bias -> out ----
    const int cgl = (lane & 3) * 2;
    const int r0l = lane >> 2;
    const float* bp = bias + n0 + wn * 64 + cgl;
    float2 bv[8];
#pragma unroll
    for (int nt = 0; nt < 8; ++nt) bv[nt] = *(const float2*)(bp + nt * 8);

#pragma unroll
    for (int mt = 0; mt < 4; ++mt) {
        size_t row = (size_t)(m0 + wm * 64 + mt * 16 + r0l);
        float* p0 = out + row * OUTF + n0 + wn * 64 + cgl;
        float* p1 = p0 + (size_t)8 * OUTF;
#pragma unroll
        for (int nt = 0; nt < 8; ++nt) {
            float2 v0 = {acc[mt][nt][0] + bv[nt].x, acc[mt][nt][1] + bv[nt].y};
            float2 v1 = {acc[mt][nt][2] + bv[nt].x, acc[mt][nt][3] + bv[nt].y};
            *(float2*)(p0 + nt * 8) = v0;
            *(float2*)(p1 + nt * 8) = v1;
        }
    }
}

// ---------------- launcher ----------------
extern "C" void kernel_launch(void* const* d_in, const int* in_sizes, int n_in,
                              void* d_out, int out_size) {
    const float* x      = (const float*)d_in[0];
    const float* logits = (const float*)d_in[1];
    const float* luts   = (const float*)d_in[2];
    const float* bias   = (const float*)d_in[3];
    float* out          = (float*)d_out;
    (void)in_sizes; (void)n_in; (void)out_size;

    split_x_kernel<<<(TOKENS * INF / 4) / 256, 256>>>(x);
    build_w_kernel<<<(OUTF * GROUPS) / 256, 256>>>(logits, luts);

    cudaFuncSetAttribute(gemm_split_kernel, cudaFuncAttributeMaxDynamicSharedMemorySize, SMEM_BYTES);
    dim3 grid(OUTF / NTILE, TOKENS / MTILE);   // (32, 32): n fast -> W stays L2-resident
    gemm_split_kernel<<<grid, 256, SMEM_BYTES>>>(bias, out);
}